// round 14
// speedup vs baseline: 6.6289x; 1.0879x over previous
#include <cuda_runtime.h>
#include <cuda_fp16.h>
#include <cstdint>

#define BB 1024
#define NQQ 64
#define CC 512
#define NH 8
#define NELEM (BB*NQQ*CC)       // 33554432
#define PER_BATCH (NQQ*CC)      // 32768
#define WPLANE4 (4096*512)      // 2097152

typedef __half fp16;

// ---------------- scratch ---------------------------------------------------
__device__ float g_xmean[PER_BATCH];

__device__ fp16 g_x16[NELEM], g_x216[NELEM];
__device__ fp16 g_mixq16[NELEM];
__device__ fp16 g_mqth[NELEM];
__device__ fp16 g_q16[NELEM], g_k16[NELEM], g_v16[NELEM];
__device__ fp16 g_yt16[NELEM];
__device__ fp16 g_convh[NELEM];
__device__ fp16 g_qf16[NELEM];
__device__ fp16 g_rgbk16[NELEM], g_infk16[NELEM];
__device__ fp16 g_rgbv16[NELEM], g_infv16[NELEM];
__device__ fp16 g_aAh[NELEM], g_aAl[NELEM];
__device__ fp16 g_aBh[NELEM], g_aBl[NELEM];
__device__ fp16 g_vph[36 * WPLANE4];
__device__ fp16 g_wu16[36 * 262144];
__device__ fp16 g_mw[36 * WPLANE4];

// fp16 weight pool
#define W16_CAQ   0
#define W16_CAK   262144
#define W16_CAV   524288
#define W16_MIXQP 786432
#define W16_RGBK  1048576
#define W16_RGBV  1310720
#define W16_INFK  1572864
#define W16_INFV  1835008
#define W16_MIXQ  2097152
#define W16_RGBO  2621440
#define W16_INFO  2883584
__device__ fp16 g_w16[3145728];

// ---------------- PTX helpers ----------------------------------------------
__device__ __forceinline__ uint32_t smem_u32(const void* p) {
    uint32_t a;
    asm("{ .reg .u64 t; cvta.to.shared.u64 t, %1; cvt.u32.u64 %0, t; }" : "=r"(a) : "l"(p));
    return a;
}
#define CP16(dst, src) \
    asm volatile("cp.async.cg.shared.global [%0], [%1], 16;" :: "r"(dst), "l"(src))
#define CPCOMMIT() asm volatile("cp.async.commit_group;" ::: "memory")
#define CPWAIT1()  asm volatile("cp.async.wait_group 1;" ::: "memory")

#define LDSM4(r, a) \
    asm volatile("ldmatrix.sync.aligned.m8n8.x4.shared.b16 {%0,%1,%2,%3}, [%4];" \
        : "=r"((r)[0]), "=r"((r)[1]), "=r"((r)[2]), "=r"((r)[3]) : "r"(a))

#define LDSM4T(r, a) \
    asm volatile("ldmatrix.sync.aligned.m8n8.x4.trans.shared.b16 {%0,%1,%2,%3}, [%4];" \
        : "=r"((r)[0]), "=r"((r)[1]), "=r"((r)[2]), "=r"((r)[3]) : "r"(a))

#define MMA16816H(d, a, b0, b1) \
    asm volatile("mma.sync.aligned.m16n8k16.row.col.f32.f16.f16.f32 " \
        "{%0,%1,%2,%3}, {%4,%5,%6,%7}, {%8,%9}, {%0,%1,%2,%3};" \
        : "+f"((d)[0]), "+f"((d)[1]), "+f"((d)[2]), "+f"((d)[3]) \
        : "r"((a)[0]), "r"((a)[1]), "r"((a)[2]), "r"((a)[3]), "r"(b0), "r"(b1))

#define PLANE_B   18432
#define STAGE1_B  (2*PLANE_B)
#define SMEM1_BYTES (3*STAGE1_B)        // 110592
#define STAGE2_B  (3*PLANE_B)
#define SMEM2_BYTES (3*STAGE2_B)        // 165888

// attention smem plane pitch: 64 halves padded to 144B (same as GEMM planes)
#define APL 9216                        // 64*144

// ---------------- stage loaders (GEMM) --------------------------------------
__device__ __forceinline__ void gemm1_load_stage(
    uint32_t smb, int stage, int t, int bm, int bn, int tid,
    const fp16* A, const fp16* A2, int ksplit, int K, const fp16* W)
{
    const int k0 = t << 6;
    const fp16* pA; int astr, acol;
    if (k0 < ksplit) { pA = A;  astr = ksplit;     acol = k0; }
    else             { pA = A2; astr = K - ksplit; acol = k0 - ksplit; }
    const uint32_t sb = smb + stage * STAGE1_B;
#pragma unroll
    for (int i = 0; i < 8; i++) {
        const int c = i * 256 + tid;
        const int plane = c >> 10, idx = c & 1023;
        const int row = idx >> 3, kc = idx & 7;
        const uint32_t dst = sb + plane * PLANE_B + row * 144 + kc * 16;
        const fp16* src = (plane == 0)
            ? pA + (size_t)(bm * 128 + row) * astr + acol + kc * 8
            : W + (size_t)(bn * 128 + row) * K + k0 + kc * 8;
        CP16(dst, src);
    }
}

__device__ __forceinline__ void gemm2_load_stage(
    uint32_t smb, int stage, int t, int bm, int bn, int tid,
    const fp16* Ah, const fp16* Al, int K, const fp16* W)
{
    const int k0 = t << 6;
    const uint32_t sb = smb + stage * STAGE2_B;
#pragma unroll
    for (int i = 0; i < 12; i++) {
        const int c = i * 256 + tid;
        const int plane = c >> 10, idx = c & 1023;
        const int row = idx >> 3, kc = idx & 7;
        const uint32_t dst = sb + plane * PLANE_B + row * 144 + kc * 16;
        const fp16* src;
        if (plane == 0)      src = Ah + (size_t)(bm * 128 + row) * K + k0 + kc * 8;
        else if (plane == 1) src = Al + (size_t)(bm * 128 + row) * K + k0 + kc * 8;
        else                 src = W + (size_t)(bn * 128 + row) * K + k0 + kc * 8;
        CP16(dst, src);
    }
}

// ---------------- GEMM compute/epilogue macros ------------------------------
#define COMPUTE_STAGE1(stg)                                                     \
    {                                                                           \
        const uint32_t sb = smb + (stg) * STAGE1_B;                             \
        const uint32_t abase = sb + (warp_m * 32 + (lane & 15)) * 144           \
                                  + ((lane >> 4) * 16);                         \
        const uint32_t bbase = sb + PLANE_B                                     \
                                  + (warp_n * 64 + (lane & 15)) * 144           \
                                  + ((lane >> 4) * 16);                         \
        _Pragma("unroll")                                                       \
        for (int ks = 0; ks < 4; ks++) {                                        \
            uint32_t fa[2][4], fb[4][4];                                        \
            _Pragma("unroll")                                                   \
            for (int mt = 0; mt < 2; mt++)                                      \
                LDSM4(fa[mt], abase + mt * (16 * 144) + ks * 32);               \
            _Pragma("unroll")                                                   \
            for (int n2 = 0; n2 < 4; n2++)                                      \
                LDSM4(fb[n2], bbase + n2 * (16 * 144) + ks * 32);               \
            _Pragma("unroll")                                                   \
            for (int mt = 0; mt < 2; mt++)                                      \
                _Pragma("unroll")                                               \
                for (int nt = 0; nt < 8; nt++) {                                \
                    const int n2 = nt >> 1, s = nt & 1;                         \
                    MMA16816H(acc[mt][nt], fa[mt], fb[n2][s], fb[n2][2 + s]);   \
                }                                                               \
        }                                                                       \
    }

#define COMPUTE_STAGE2(stg)                                                     \
    {                                                                           \
        const uint32_t sb = smb + (stg) * STAGE2_B;                             \
        const uint32_t abase = sb + (warp_m * 32 + (lane & 15)) * 144           \
                                  + ((lane >> 4) * 16);                         \
        const uint32_t bbase = sb + 2 * PLANE_B                                 \
                                  + (warp_n * 64 + (lane & 15)) * 144           \
                                  + ((lane >> 4) * 16);                         \
        _Pragma("unroll")                                                       \
        for (int ks = 0; ks < 4; ks++) {                                        \
            uint32_t fah[2][4], fal[2][4], fb[4][4];                            \
            _Pragma("unroll")                                                   \
            for (int mt = 0; mt < 2; mt++) {                                    \
                const uint32_t a = abase + mt * (16 * 144) + ks * 32;           \
                LDSM4(fah[mt], a);                                              \
                LDSM4(fal[mt], a + PLANE_B);                                    \
            }                                                                   \
            _Pragma("unroll")                                                   \
            for (int n2 = 0; n2 < 4; n2++)                                      \
                LDSM4(fb[n2], bbase + n2 * (16 * 144) + ks * 32);               \
            _Pragma("unroll")                                                   \
            for (int mt = 0; mt < 2; mt++)                                      \
                _Pragma("unroll")                                               \
                for (int nt = 0; nt < 8; nt++) {                                \
                    const int n2 = nt >> 1, s = nt & 1;                         \
                    MMA16816H(acc[mt][nt], fah[mt], fb[n2][s], fb[n2][2 + s]);  \
                    MMA16816H(acc[mt][nt], fal[mt], fb[n2][s], fb[n2][2 + s]);  \
                }                                                               \
        }                                                                       \
    }

#define EPILOGUE_F()                                                            \
    {                                                                           \
        const int lrow = lane >> 2, lcol = (lane & 3) * 2;                      \
        _Pragma("unroll")                                                       \
        for (int mt = 0; mt < 2; mt++)                                          \
            _Pragma("unroll")                                                   \
            for (int nt = 0; nt < 8; nt++) {                                    \
                const int row = bm * 128 + warp_m * 32 + mt * 16 + lrow;        \
                const int col = bn * 128 + warp_n * 64 + nt * 8 + lcol;         \
                const float b0 = bias[col], b1 = bias[col + 1];                 \
                float2 v0 = make_float2(acc[mt][nt][0] + b0, acc[mt][nt][1] + b1); \
                float2 v1 = make_float2(acc[mt][nt][2] + b0, acc[mt][nt][3] + b1); \
                *(float2*)(C + (size_t)row * 512 + col) = v0;                   \
                *(float2*)(C + (size_t)(row + 8) * 512 + col) = v1;             \
            }                                                                   \
    }

#define EPILOGUE_HB_SPLIT()                                                     \
    {                                                                           \
        const int tsel = bn >> 2;                                               \
        fp16* C = (tsel == 0) ? C0 : ((tsel == 1) ? C1 : C2);                   \
        const float* bias = (tsel == 0) ? b0p : ((tsel == 1) ? b1p : b2p);      \
        const int bnl = bn & 3;                                                 \
        const int lrow = lane >> 2, lcol = (lane & 3) * 2;                      \
        _Pragma("unroll")                                                       \
        for (int mt = 0; mt < 2; mt++)                                          \
            _Pragma("unroll")                                                   \
            for (int nt = 0; nt < 8; nt++) {                                    \
                const int row = bm * 128 + warp_m * 32 + mt * 16 + lrow;        \
                const int col = bnl * 128 + warp_n * 64 + nt * 8 + lcol;        \
                const float b0 = bias[col], b1 = bias[col + 1];                 \
                *(__half2*)(C + (size_t)row * 512 + col) =                      \
                    __halves2half2(__float2half(acc[mt][nt][0] + b0),           \
                                   __float2half(acc[mt][nt][1] + b1));          \
                *(__half2*)(C + (size_t)(row + 8) * 512 + col) =                \
                    __halves2half2(__float2half(acc[mt][nt][2] + b0),           \
                                   __float2half(acc[mt][nt][3] + b1));          \
            }                                                                   \
    }

#define EPILOGUE_H()                                                            \
    {                                                                           \
        const int lrow = lane >> 2, lcol = (lane & 3) * 2;                      \
        _Pragma("unroll")                                                       \
        for (int mt = 0; mt < 2; mt++)                                          \
            _Pragma("unroll")                                                   \
            for (int nt = 0; nt < 8; nt++) {                                    \
                const int row = bm * 128 + warp_m * 32 + mt * 16 + lrow;        \
                const int col = bn * 128 + warp_n * 64 + nt * 8 + lcol;         \
                *(__half2*)(C + (size_t)row * 512 + col) =                      \
                    __halves2half2(__float2half(acc[mt][nt][0]),                \
                                   __float2half(acc[mt][nt][1]));               \
                *(__half2*)(C + (size_t)(row + 8) * 512 + col) =                \
                    __halves2half2(__float2half(acc[mt][nt][2]),                \
                                   __float2half(acc[mt][nt][3]));               \
            }                                                                   \
    }

#define MAINLOOP(LOADER, COMPUTE, ...)                                          \
    {                                                                           \
        LOADER(smb, 0, 0, bm, bn, tid, __VA_ARGS__);                            \
        CPCOMMIT();                                                             \
        LOADER(smb, 1, 1, bm, bn, tid, __VA_ARGS__);                            \
        CPCOMMIT();                                                             \
        int s_cur = 0, s_nxt = 2;                                               \
        for (int t = 0; t < NT; t++) {                                          \
            CPWAIT1();                                                          \
            __syncthreads();                                                    \
            if (t + 2 < NT)                                                     \
                LOADER(smb, s_nxt, t + 2, bm, bn, tid, __VA_ARGS__);            \
            CPCOMMIT();                                                         \
            COMPUTE(s_cur);                                                     \
            s_cur = (s_cur == 2) ? 0 : s_cur + 1;                               \
            s_nxt = (s_nxt == 2) ? 0 : s_nxt + 1;                               \
        }                                                                       \
    }

#define ACC_INIT()                                                              \
    float acc[2][8][4];                                                         \
    _Pragma("unroll")                                                           \
    for (int i = 0; i < 2; i++)                                                 \
        _Pragma("unroll")                                                       \
        for (int j = 0; j < 8; j++)                                             \
            _Pragma("unroll")                                                   \
            for (int k = 0; k < 4; k++) acc[i][j][k] = 0.f;

#define GEMM_PREAMBLE()                                                         \
    extern __shared__ char sm[];                                                \
    const uint32_t smb = smem_u32(sm);                                          \
    const int tid = threadIdx.x, lane = tid & 31, wid = tid >> 5;               \
    const int warp_m = wid & 3, warp_n = wid >> 2;                              \
    const int bn = blockIdx.x, bm = blockIdx.y;

// ---------------- fp16x1 GEMM, split fp16 out -------------------------------
__global__ __launch_bounds__(256, 2) void gemm_h1h(
    const fp16* __restrict__ A, const fp16* __restrict__ A2,
    int ksplit, int K, const fp16* __restrict__ W,
    const float* __restrict__ b0p, const float* __restrict__ b1p,
    const float* __restrict__ b2p,
    fp16* __restrict__ C0, fp16* __restrict__ C1, fp16* __restrict__ C2)
{
    GEMM_PREAMBLE();
    ACC_INIT();
    const int NT = K >> 6;
    MAINLOOP(gemm1_load_stage, COMPUTE_STAGE1, A, A2, ksplit, K, W);
    EPILOGUE_HB_SPLIT();
}

// ---------------- fp16x2 GEMM, fp32 out -------------------------------------
__global__ __launch_bounds__(256, 1) void gemm_h2f(
    const fp16* __restrict__ Ah, const fp16* __restrict__ Al,
    int K, const fp16* __restrict__ W,
    const float* __restrict__ bias, float* __restrict__ C)
{
    GEMM_PREAMBLE();
    ACC_INIT();
    const int NT = K >> 6;
    MAINLOOP(gemm2_load_stage, COMPUTE_STAGE2, Ah, Al, K, W);
    EPILOGUE_F();
}

// ---------------- winograd F(4x4) batched GEMM ------------------------------
__global__ __launch_bounds__(256, 2) void wino_gemm4(
    const fp16* __restrict__ V, const fp16* __restrict__ U, fp16* __restrict__ Mb)
{
    extern __shared__ char sm[];
    const uint32_t smb = smem_u32(sm);
    const int tid = threadIdx.x, lane = tid & 31, wid = tid >> 5;
    const int warp_m = wid & 3, warp_n = wid >> 2;
    const int bn = blockIdx.x, bm = blockIdx.y, z = blockIdx.z;
    const fp16* A = V + (size_t)z * WPLANE4;
    const fp16* W = U + (size_t)z * 262144;
    fp16* C = Mb + (size_t)z * WPLANE4;
    ACC_INIT();
    const int NT = 8;
    MAINLOOP(gemm1_load_stage, COMPUTE_STAGE1, A, A, 512, 512, W);
    EPILOGUE_H();
}

// ---------------- winograd F(4x4) transforms --------------------------------
__device__ __forceinline__ void gmul6(const float x0, const float x1, const float x2,
                                      float* y)
{
    y[0] = 0.25f * x0;
    y[1] = (-1.0f / 6.0f) * (x0 + x1 + x2);
    y[2] = (-1.0f / 6.0f) * (x0 - x1 + x2);
    y[3] = (1.0f / 24.0f) * (x0 + 2.0f * x1 + 4.0f * x2);
    y[4] = (1.0f / 24.0f) * (x0 - 2.0f * x1 + 4.0f * x2);
    y[5] = x2;
}

__global__ void wg_weight4(const float* __restrict__ cw, fp16* __restrict__ u16)
{
    const int idx = blockIdx.x * 256 + threadIdx.x;
    const int o = idx >> 9, c = idx & 511;
    const float* g = cw + (size_t)(o * 512 + c) * 9;
    float P[6][3];
#pragma unroll
    for (int kj = 0; kj < 3; kj++) {
        float col[6];
        gmul6(g[0 * 3 + kj], g[1 * 3 + kj], g[2 * 3 + kj], col);
#pragma unroll
        for (int r = 0; r < 6; r++) P[r][kj] = col[r];
    }
#pragma unroll
    for (int r = 0; r < 6; r++) {
        float U[6];
        gmul6(P[r][0], P[r][1], P[r][2], U);
#pragma unroll
        for (int cc = 0; cc < 6; cc++)
            u16[(size_t)(r * 6 + cc) * 262144 + o * 512 + c] = __float2half(U[cc]);
    }
}

__device__ __forceinline__ void btmul6(const float* x, float* y)
{
    y[0] = 4.0f * x[0] - 5.0f * x[2] + x[4];
    y[1] = -4.0f * x[1] - 4.0f * x[2] + x[3] + x[4];
    y[2] = 4.0f * x[1] - 4.0f * x[2] - x[3] + x[4];
    y[3] = -2.0f * x[1] - x[2] + 2.0f * x[3] + x[4];
    y[4] = 2.0f * x[1] - x[2] - 2.0f * x[3] + x[4];
    y[5] = 4.0f * x[1] - 5.0f * x[3] + x[5];
}

__global__ void wg_input4(const fp16* __restrict__ yt, fp16* __restrict__ vh)
{
    const int idx = blockIdx.x * 256 + threadIdx.x;
    const int c = idx & 511;
    const int m = idx >> 9;
    const int b = m >> 2, t = m & 3;
    const int ti = t >> 1, tj = t & 1;
    const int r0 = 4 * ti - 1, c0 = 4 * tj - 1;
    float d[6][6];
#pragma unroll
    for (int r = 0; r < 6; r++) {
        const int ir = r0 + r;
#pragma unroll
        for (int cc = 0; cc < 6; cc++) {
            const int jc = c0 + cc;
            d[r][cc] = ((unsigned)ir < 8u && (unsigned)jc < 8u)
                ? __half2float(yt[((size_t)b * 64 + ir * 8 + jc) * 512 + c]) : 0.f;
        }
    }
    float p[6][6];
#pragma unroll
    for (int cc = 0; cc < 6; cc++) {
        float col[6], out[6];
#pragma unroll
        for (int r = 0; r < 6; r++) col[r] = d[r][cc];
        btmul6(col, out);
#pragma unroll
        for (int r = 0; r < 6; r++) p[r][cc] = out[r];
    }
#pragma unroll
    for (int r = 0; r < 6; r++) {
        float V[6];
        btmul6(p[r], V);
#pragma unroll
        for (int cc = 0; cc < 6; cc++)
            vh[(size_t)(r * 6 + cc) * WPLANE4 + (size_t)m * 512 + c] = __float2half(V[cc]);
    }
}

__device__ __forceinline__ void atmul6(const float* x, float* z)
{
    z[0] = x[0] + x[1] + x[2] + x[3] + x[4];
    z[1] = x[1] - x[2] + 2.0f * x[3] - 2.0f * x[4];
    z[2] = x[1] + x[2] + 4.0f * x[3] + 4.0f * x[4];
    z[3] = x[1] - x[2] + 8.0f * x[3] - 8.0f * x[4] + x[5];
}

__global__ void wg_output4(const fp16* __restrict__ Mb, const float* __restrict__ bias,
                           fp16* __restrict__ ch)
{
    const int idx = blockIdx.x * 256 + threadIdx.x;
    const int o = idx & 511;
    const int m = idx >> 9;
    const int b = m >> 2, t = m & 3;
    const int ti = t >> 1, tj = t & 1;
    float M[6][6];
#pragma unroll
    for (int f = 0; f < 36; f++)
        M[f / 6][f % 6] = __half2float(Mb[(size_t)f * WPLANE4 + (size_t)m * 512 + o]);
    float P[4][6];
#pragma unroll
    for (int cc = 0; cc < 6; cc++) {
        float col[6], out[4];
#pragma unroll
        for (int r = 0; r < 6; r++) col[r] = M[r][cc];
        atmul6(col, out);
#pragma unroll
        for (int r = 0; r < 4; r++) P[r][cc] = out[r];
    }
    const float bv = bias[o];
#pragma unroll
    for (int di = 0; di < 4; di++) {
        float O[4];
        atmul6(P[di], O);
        const size_t s0 = ((size_t)b * 64 + (4 * ti + di) * 8 + 4 * tj) * 512 + o;
#pragma unroll
        for (int dj = 0; dj < 4; dj++)
            ch[s0 + (size_t)dj * 512] = __float2half(O[dj] + bv);
    }
}

// ---------------- conversions -----------------------------------------------
// x and x2 in one launch (blockIdx.y selects)
__global__ void cvt_inputs(const float* __restrict__ x, const float* __restrict__ x2,
                           fp16* __restrict__ dx, fp16* __restrict__ dx2)
{
    const int i = blockIdx.x * 256 + threadIdx.x;
    const float* s = blockIdx.y ? x2 : x;
    fp16* d = blockIdx.y ? dx2 : dx;
    float4 v = ((const float4*)s)[i];
    ((__half2*)d)[i * 2 + 0] = __halves2half2(__float2half(v.x), __float2half(v.y));
    ((__half2*)d)[i * 2 + 1] = __halves2half2(__float2half(v.z), __float2half(v.w));
}

// all 11 weight conversions in one launch
__global__ void wcvt_all(
    const float* w0, const float* w1, const float* w2, const float* w3,
    const float* w4, const float* w5, const float* w6, const float* w7,
    const float* w8, const float* w9, const float* w10, fp16* __restrict__ dst)
{
    const int blk = blockIdx.x;
    const float* src;
    size_t doff;
    int lb;
    if (blk < 512) { src = w0; doff = W16_MIXQ; lb = blk; }
    else {
        const int t = (blk - 512) >> 8;
        lb = (blk - 512) & 255;
        switch (t) {
            case 0: src = w1;  doff = W16_CAQ;   break;
            case 1: src = w2;  doff = W16_CAK;   break;
            case 2: src = w3;  doff = W16_CAV;   break;
            case 3: src = w4;  doff = W16_MIXQP; break;
            case 4: src = w5;  doff = W16_RGBK;  break;
            case 5: src = w6;  doff = W16_RGBV;  break;
            case 6: src = w7;  doff = W16_INFK;  break;
            case 7: src = w8;  doff = W16_INFV;  break;
            case 8: src = w9;  doff = W16_RGBO;  break;
            default: src = w10; doff = W16_INFO;  break;
        }
    }
    const int i = lb * 256 + threadIdx.x;
    float4 v = ((const float4*)src)[i];
    ((__half2*)(dst + doff))[i * 2 + 0] = __halves2half2(__float2half(v.x), __float2half(v.y));
    ((__half2*)(dst + doff))[i * 2 + 1] = __halves2half2(__float2half(v.z), __float2half(v.w));
}

// ---------------- tensor-core attention helpers ------------------------------
__device__ __forceinline__ void ld_tile64(const fp16* g, size_t base, char* sp, int tid)
{
#pragma unroll
    for (int i = tid; i < 512; i += 256) {
        const int r = i >> 3, c = i & 7;
        *(uint4*)(sp + r * 144 + c * 16) = *(const uint4*)(g + base + (size_t)r * 512 + c * 8);
    }
}

__device__ __forceinline__ void softmax64(float* S, int tid)
{
    const int warp = tid >> 5, lane = tid & 31;
    for (int r = warp * 8; r < warp * 8 + 8; r++) {
        float v0 = S[r * 64 + lane];
        float v1 = S[r * 64 + 32 + lane];
        float m = fmaxf(v0, v1);
#pragma unroll
        for (int o = 16; o > 0; o >>= 1) m = fmaxf(m, __shfl_xor_sync(0xffffffffu, m, o));
        float e0 = __expf(v0 - m);
        float e1 = __expf(v1 - m);
        float sum = e0 + e1;
#pragma unroll
        for (int o = 16; o > 0; o >>= 1) sum += __shfl_xor_sync(0xffffffffu, sum, o);
        float inv = 1.0f / sum;
        S[r * 64 + lane]      = e0 * inv;
        S[r * 64 + 32 + lane] = e1 * inv;
    }
}

// ---------------- CA attention (HMMA) + fused combine ------------------------
// smem: Q 0, K APL, V 2*APL, S fp32 3*APL (16KB), Ph 3*APL+16384
#define CA_SMEM (3*APL + 16384 + APL)   // 53248
__global__ __launch_bounds__(256, 2) void attn_ca(
    const fp16* __restrict__ Q, const fp16* __restrict__ Kp, const fp16* __restrict__ Vp,
    const float* __restrict__ XM, const fp16* __restrict__ MQ,
    const float* __restrict__ GM, fp16* __restrict__ YT, float scale)
{
    extern __shared__ char smc[];
    const uint32_t smb = smem_u32(smc);
    float* S = (float*)(smc + 3 * APL);
    const int tid = threadIdx.x, lane = tid & 31, wid = tid >> 5;
    const int warp_m = wid & 3, warp_n = wid >> 2;
    const int bh = blockIdx.x;
    const int b = bh >> 3, h = bh & 7;
    const size_t base = (size_t)b * 64 * 512 + h * 64;

    ld_tile64(Q, base, smc, tid);
    ld_tile64(Kp, base, smc + APL, tid);
    ld_tile64(Vp, base, smc + 2 * APL, tid);
    __syncthreads();

    // QK^T
    float acc[4][4];
#pragma unroll
    for (int i = 0; i < 4; i++)
#pragma unroll
        for (int j = 0; j < 4; j++) acc[i][j] = 0.f;
    {
        const uint32_t qb = smb + (warp_m * 16 + (lane & 15)) * 144 + (lane >> 4) * 16;
        const uint32_t kb = smb + APL + (warp_n * 32 + (lane & 15)) * 144 + (lane >> 4) * 16;
#pragma unroll
        for (int ks = 0; ks < 4; ks++) {
            uint32_t fa[4], fb[2][4];
            LDSM4(fa, qb + ks * 32);
#pragma unroll
            for (int n2 = 0; n2 < 2; n2++)
                LDSM4(fb[n2], kb + n2 * (16 * 144) + ks * 32);
#pragma unroll
            for (int nt = 0; nt < 4; nt++) {
                const int n2 = nt >> 1, s = nt & 1;
                MMA16816H(acc[nt], fa, fb[n2][s], fb[n2][2 + s]);
            }
        }
    }
    // write S = acc*scale
    {
        const int r0 = warp_m * 16 + (lane >> 2);
#pragma unroll
        for (int nt = 0; nt < 4; nt++) {
            const int col = warp_n * 32 + nt * 8 + (lane & 3) * 2;
            S[r0 * 64 + col]     = acc[nt][0] * scale;
            S[r0 * 64 + col + 1] = acc[nt][1] * scale;
            S[(r0 + 8) * 64 + col]     = acc[nt][2] * scale;
            S[(r0 + 8) * 64 + col + 1] = acc[nt][3] * scale;
        }
    }
    __syncthreads();
    softmax64(S, tid);
    __syncthreads();
    // P -> fp16 (hi only; CA is logit path)
    {
        char* Ph = smc + 3 * APL + 16384;
        for (int i = tid; i < 4096; i += 256) {
            const int r = i >> 6, c = i & 63;
            *(fp16*)(Ph + r * 144 + c * 2) = __float2half(S[i]);
        }
    }
    __syncthreads();
    // P @ V
    float o[4][4];
#pragma unroll
    for (int i = 0; i < 4; i++)
#pragma unroll
        for (int j = 0; j < 4; j++) o[i][j] = 0.f;
    {
        const uint32_t pb = smb + 3 * APL + 16384
                          + (warp_m * 16 + (lane & 15)) * 144 + (lane >> 4) * 16;
        const uint32_t vb = smb + 2 * APL + (lane & 15) * 144 + (lane >> 4) * 16;
#pragma unroll
        for (int ks = 0; ks < 4; ks++) {
            uint32_t fa[4], fv[2][4];
            LDSM4(fa, pb + ks * 32);
#pragma unroll
            for (int n2 = 0; n2 < 2; n2++)
                LDSM4T(fv[n2], vb + ks * (16 * 144) + warp_n * 64 + n2 * 32);
#pragma unroll
            for (int nt = 0; nt < 4; nt++) {
                const int n2 = nt >> 1, s = nt & 1;
                MMA16816H(o[nt], fa, fv[n2][2 * s], fv[n2][2 * s + 1]);
            }
        }
    }
    // fused combine epilogue
    const float g = GM[0];
    {
        const int r0 = warp_m * 16 + (lane >> 2);
#pragma unroll
        for (int nt = 0; nt < 4; nt++) {
            const int col = warp_n * 32 + nt * 8 + (lane & 3) * 2;
#pragma unroll
            for (int hh = 0; hh < 2; hh++) {
                const int row = r0 + hh * 8;
                const size_t off = (size_t)(b * 64 + row) * 512 + h * 64 + col;
                const int mo = (int)(off & (PER_BATCH - 1));
                float2 xm = *(const float2*)(XM + mo);
                float2 mq = __half22float2(*(const __half2*)(MQ + off));
                *(__half2*)(YT + off) = __halves2half2(
                    __float2half(xm.x + g * o[nt][2 * hh]     + mq.x),
                    __float2half(xm.y + g * o[nt][2 * hh + 1] + mq.y));
            }
        }
    }
}

// ---------------- dual masked attention (HMMA, fp16 hi/lo out) ---------------
// smem: Q 0, IK APL, RK 2APL, V 3APL, SA fp32 4APL, SB 4APL+16K,
//       PAh 4APL+32K, PAl +APL, PBh +2APL, PBl +3APL
#define DU_SA   (4*APL)
#define DU_SB   (4*APL + 16384)
#define DU_P    (4*APL + 32768)
#define DU_SMEM (DU_P + 4*APL)          // 105472... (4*9216+32768+4*9216 = 106624? compute: 36864+32768+36864 = 106496)
__global__ __launch_bounds__(256, 2) void attn_dual(
    const fp16* __restrict__ Q,
    const fp16* __restrict__ IK, const fp16* __restrict__ RK,
    const fp16* __restrict__ RV, const fp16* __restrict__ IV,
    const float* __restrict__ AW, const int* __restrict__ MK,
    fp16* __restrict__ AH, fp16* __restrict__ AL,
    fp16* __restrict__ BH, fp16* __restrict__ BL, float scale)
{
    extern __shared__ char smc[];
    const uint32_t smb = smem_u32(smc);
    float* SA = (float*)(smc + DU_SA);
    float* SB = (float*)(smc + DU_SB);
    const float NEG_INF = __int_as_float(0xff800000);
    const int tid = threadIdx.x, lane = tid & 31, wid = tid >> 5;
    const int warp_m = wid & 3, warp_n = wid >> 2;
    const int bh = blockIdx.x;
    const int b = bh >> 3, h = bh & 7;
    const size_t base = (size_t)b * 64 * 512 + h * 64;

    ld_tile64(Q, base, smc, tid);
    ld_tile64(IK, base, smc + APL, tid);
    ld_tile64(RK, base, smc + 2 * APL, tid);
    __syncthreads();

    // dual QK^T
    float accA[4][4], accB[4][4];
#pragma unroll
    for (int i = 0; i < 4; i++)
#pragma unroll
        for (int j = 0; j < 4; j++) { accA[i][j] = 0.f; accB[i][j] = 0.f; }
    {
        const uint32_t qb = smb + (warp_m * 16 + (lane & 15)) * 144 + (lane >> 4) * 16;
        const uint32_t ib = smb + APL + (warp_n * 32 + (lane & 15)) * 144 + (lane >> 4) * 16;
        const uint32_t rb = smb + 2 * APL + (warp_n * 32 + (lane & 15)) * 144 + (lane >> 4) * 16;
#pragma unroll
        for (int ks = 0; ks < 4; ks++) {
            uint32_t fa[4], fi[2][4], fr[2][4];
            LDSM4(fa, qb + ks * 32);
#pragma unroll
            for (int n2 = 0; n2 < 2; n2++) {
                LDSM4(fi[n2], ib + n2 * (16 * 144) + ks * 32);
                LDSM4(fr[n2], rb + n2 * (16 * 144) + ks * 32);
            }
#pragma unroll
            for (int nt = 0; nt < 4; nt++) {
                const int n2 = nt >> 1, s = nt & 1;
                MMA16816H(accA[nt], fa, fi[n2][s], fi[n2][2 + s]);
                MMA16816H(accB[nt], fa, fr[n2][s], fr[n2][2 + s]);
            }
        }
    }
    // write S with scale*aw, mask -> -inf
    {
        const size_t ab = (size_t)bh * 4096;
        const int r0 = warp_m * 16 + (lane >> 2);
#pragma unroll
        for (int nt = 0; nt < 4; nt++) {
            const int col = warp_n * 32 + nt * 8 + (lane & 3) * 2;
#pragma unroll
            for (int hh = 0; hh < 2; hh++) {
                const int row = r0 + hh * 8;
                const size_t off = ab + (size_t)row * 64 + col;
                float2 w = *(const float2*)(AW + off);
                int2 m = *(const int2*)(MK + off);
                SA[row * 64 + col]     = m.x ? NEG_INF : accA[nt][2 * hh] * scale * w.x;
                SA[row * 64 + col + 1] = m.y ? NEG_INF : accA[nt][2 * hh + 1] * scale * w.y;
                SB[row * 64 + col]     = m.x ? NEG_INF : accB[nt][2 * hh] * scale * w.x;
                SB[row * 64 + col + 1] = m.y ? NEG_INF : accB[nt][2 * hh + 1] * scale * w.y;
            }
        }
    }
    __syncthreads();
    softmax64(SA, tid);
    softmax64(SB, tid);
    __syncthreads();
    // P -> fp16 hi/lo (direct path: exact split)
    {
        char* P = smc + DU_P;
        for (int i = tid; i < 4096; i += 256) {
            const int r = i >> 6, c = i & 63;
            float va = SA[i];
            fp16 ha = __float2half(va);
            *(fp16*)(P + r * 144 + c * 2)            = ha;
            *(fp16*)(P + APL + r * 144 + c * 2)      = __float2half(va - __half2float(ha));
            float vb = SB[i];
            fp16 hb = __float2half(vb);
            *(fp16*)(P + 2 * APL + r * 144 + c * 2)  = hb;
            *(fp16*)(P + 3 * APL + r * 144 + c * 2)  = __float2half(vb - __half2float(hb));
        }
    }
    // two value passes
#pragma unroll
    for (int pass = 0; pass < 2; pass++) {
        ld_tile64(pass ? IV : RV, base, smc + 3 * APL, tid);
        __syncthreads();
        float o[4][4];
#pragma unroll
        for (int i = 0; i < 4; i++)
#pragma unroll
            for (int j = 0; j < 4; j++) o[i][j] = 0.f;
        const uint32_t ph = smb + DU_P + (pass ? 2 * APL : 0)
                          + (warp_m * 16 + (lane & 15)) * 144 + (lane >> 4) * 16;
        const uint32_t vb = smb + 3 * APL + (lane & 15) * 144 + (lane >> 4) * 16;
#pragma unroll
        for (int ks = 0; ks < 4; ks++) {
            uint32_t fah[4], fal[4], fv[2][4];
            LDSM4(fah, ph + ks * 32);
            LDSM4(fal, ph + APL + ks * 32);
#pragma unroll
            for (int n2 = 0; n2 < 2; n2++)
                LDSM4T(fv[n2], vb + ks * (16 * 144) + warp_n * 64 + n2 * 32);
#pragma unroll
            for (int nt = 0; nt < 4; nt++) {
                const int n2 = nt >> 1, s = nt & 1;
                MMA16816H(o[nt], fah, fv[n2][2 * s], fv[n2][2 * s + 1]);
                MMA16816H(o[nt], fal, fv[n2][2 * s], fv[n2][2 * s + 1]);
            }
        }
        fp16* OH = pass ? BH : AH;
        fp16* OL = pass ? BL : AL;
        const int r0 = warp_m * 16 + (lane >> 2);
#pragma unroll
        for (int nt = 0; nt < 4; nt++) {
            const int col = warp_n * 32 + nt * 8 + (lane & 3) * 2;
#pragma unroll
            for (int hh = 0; hh < 2; hh++) {
                const int row = r0 + hh * 8;
                const size_t off = (size_t)(b * 64 + row) * 512 + h * 64 + col;
                float v0 = o[nt][2 * hh], v1 = o[nt][2 * hh + 1];
                fp16 h0 = __float2half(v0), h1 = __float2half(v1);
                *(__half2*)(OH + off) = __halves2half2(h0, h1);
                *(__half2*)(OL + off) = __halves2half2(
                    __float2half(v0 - __half2float(h0)),
                    __float2half(v1 - __half2float(h1)));
            }
        }
        __syncthreads();
    }
}

// ---------------- small helpers -------------------------------------------
__global__ void transpose_kernel(const fp16* __restrict__ src, fp16* __restrict__ dst)
{
    __shared__ float tile[32][33];
    const int bz = blockIdx.z;
    const int c0 = blockIdx.x * 32, s0 = blockIdx.y * 32;
    const fp16* S = src + (size_t)bz * PER_BATCH;
    const size_t dbase = (size_t)bz * PER_BATCH;
    for (int r = threadIdx.y; r < 32; r += 8)
        tile[r][threadIdx.x] = __half2float(S[(c0 + r) * 64 + s0 + threadIdx.x]);
    __syncthreads();
    for (int r = threadIdx.y; r < 32; r += 8)
        dst[dbase + (size_t)(s0 + r) * 512 + c0 + threadIdx.x]
            = __float2half(tile[threadIdx.x][r]);
}

__global__ void xmean_kernel(const fp16* __restrict__ mqt, float* __restrict__ xm)
{
    const int i = blockIdx.x * 256 + threadIdx.x;
    float sum = 0.f;
#pragma unroll 8
    for (int b = 0; b < BB; b++)
        sum += __half2float(mqt[(size_t)b * PER_BATCH + i]);
    xm[i] = sum * (1.0f / (float)BB);
}

// ---------------- launch ----------------------------------------------------
extern "C" void kernel_launch(void* const* d_in, const int* in_sizes, int n_in,
                              void* d_out, int out_size)
{
    (void)in_sizes; (void)n_in; (void)out_size;
    const float* x        = (const float*)d_in[0];
    const float* x2       = (const float*)d_in[1];
    const float* aw       = (const float*)d_in[2];
    const int*   mask     = (const int*)d_in[3];
    const float* mixq_w   = (const float*)d_in[4];
    const float* mixq_b   = (const float*)d_in[5];
    const float* mixqp_w  = (const float*)d_in[6];
    const float* mixqp_b  = (const float*)d_in[7];
    const float* ca_qw    = (const float*)d_in[8];
    const float* ca_qb    = (const float*)d_in[9];
    const float* ca_kw    = (const float*)d_in[10];
    const float* ca_kb    = (const float*)d_in[11];
    const float* ca_vw    = (const float*)d_in[12];
    const float* ca_vb    = (const float*)d_in[13];
    const float* ca_gamma = (const float*)d_in[14];
    const float* cba_cw   = (const float*)d_in[15];
    const float* cba_cb   = (const float*)d_in[16];
    const float* rgbk_w   = (const float*)d_in[17];
    const float* rgbk_b   = (const float*)d_in[18];
    const float* rgbv_w   = (const float*)d_in[19];
    const float* rgbv_b   = (const float*)d_in[20];
    const float* rgbo_w   = (const float*)d_in[21];
    const float* rgbo_b   = (const float*)d_in[22];
    const float* infk_w   = (const float*)d_in[23];
    const float* infk_b   = (const float*)d_in[24];
    const float* infv_w   = (const float*)d_in[25];
    const float* infv_b   = (const float*)d_in[26];
    const float* info_w   = (const float*)d_in[27];
    const float* info_b   = (const float*)d_in[28];

    float* p_xmean;
    fp16 *p_x16, *p_x216, *p_mixq16, *p_mqth, *p_q16, *p_k16, *p_v16, *p_yt16;
    fp16 *p_convh, *p_qf16, *p_rgbk16, *p_infk16, *p_rgbv16, *p_infv16;
    fp16 *p_aAh, *p_aAl, *p_aBh, *p_aBl, *p_vph, *p_wu16, *p_w16, *p_mw;
    cudaGetSymbolAddress((void**)&p_xmean,  g_xmean);
    cudaGetSymbolAddress((void**)&p_x16,    g_x16);
    cudaGetSymbolAddress((void**)&p_x216,   g_x216);
    cudaGetSymbolAddress((void**)&p_mixq16, g_mixq16);
    cudaGetSymbolAddress((void**)&p_mqth,   g_mqth);
    cudaGetSymbolAddress((void**)&p_q16,    g_q16);
    cudaGetSymbolAddress((void**)&p_k16,    g_k16);
    cudaGetSymbolAddress((void**)&p_v16,    g_v16);
    cudaGetSymbolAddress((void**)&p_yt16,   g_yt16);
    cudaGetSymbolAddress((void**)&p_convh,  g_convh);
    cudaGetSymbolAddress((void**)&p_qf16,   g_qf16);
    cudaGetSymbolAddress((void**)&p_rgbk16, g_rgbk16);
    cudaGetSymbolAddress((void**)&p_infk16, g_infk16);
    cudaGetSymbolAddress((void**)&p_rgbv16, g_rgbv16);
    cudaGetSymbolAddress((void**)&p_infv16, g_infv16);
    cudaGetSymbolAddress((void**)&p_aAh,    g_aAh);
    cudaGetSymbolAddress((void**)&p_aAl,    g_aAl);
    cudaGetSymbolAddress((void**)&p_aBh,    g_aBh);
    cudaGetSymbolAddress((void**)&p_aBl,    g_aBl);
    cudaGetSymbolAddress((void**)&p_vph,    g_vph);
    cudaGetSymbolAddress((void**)&p_wu16,   g_wu16);
    cudaGetSymbolAddress((void**)&p_w16,    g_w16);
    cudaGetSymbolAddress((void**)&p_mw,     g_mw);

    float* out = (float*)d_out;

    cudaFuncSetAttribute(gemm_h1h,  cudaFuncAttributeMaxDynamicSharedMemorySize, SMEM1_BYTES);
    cudaFuncSetAttribute(gemm_h2f,  cudaFuncAttributeMaxDynamicSharedMemorySize, SMEM2_BYTES);
    cudaFuncSetAttribute(wino_gemm4, cudaFuncAttributeMaxDynamicSharedMemorySize, SMEM1_BYTES);
    cudaFuncSetAttribute(attn_ca,   cudaFuncAttributeMaxDynamicSharedMemorySize, CA_SMEM);
    cudaFuncSetAttribute(attn_dual, cudaFuncAttributeMaxDynamicSharedMemorySize, DU_P + 4*APL);

    const int ACT4 = NELEM / 4;
    const int ABLK = ACT4 / 256;

    // fused conversions
    cvt_inputs<<<dim3(ABLK, 2), 256>>>(x, x2, p_x16, p_x216);
    wcvt_all<<<3072, 256>>>(mixq_w, ca_qw, ca_kw, ca_vw, mixqp_w, rgbk_w, rgbv_w,
                            infk_w, infv_w, rgbo_w, info_w, p_w16);
    wg_weight4<<<1024, 256>>>(cba_cw, p_wu16);

    // 1. mix_q (fp16x1, K=1024)
    gemm_h1h<<<dim3(4, 512), 256, SMEM1_BYTES>>>(p_x16, p_x216, 512, 1024,
        p_w16 + W16_MIXQ, mixq_b, mixq_b, mixq_b, p_mixq16, p_mixq16, p_mixq16);
    // 2. raw reinterpret -> transpose (fp16), xmean
    transpose_kernel<<<dim3(16, 2, BB), dim3(32, 8)>>>(p_mixq16, p_mqth);
    xmean_kernel<<<PER_BATCH / 256, 256>>>(p_mqth, p_xmean);
    // 3. CA q|k|v in ONE launch (N=1536)
    gemm_h1h<<<dim3(12, 512), 256, SMEM1_BYTES>>>(p_mqth, p_mqth, 512, 512,
        p_w16 + W16_CAQ, ca_qb, ca_kb, ca_vb, p_q16, p_k16, p_v16);
    // 4. CA attention (HMMA) + fused combine
    attn_ca<<<BB * NH, 256, CA_SMEM>>>(p_q16, p_k16, p_v16, p_xmean, p_mqth,
                                       ca_gamma, p_yt16, 0.125f);
    // 5. conv via winograd F(4x4,3x3)
    wg_input4<<<WPLANE4 / 256, 256>>>(p_yt16, p_vph);
    wino_gemm4<<<dim3(4, 32, 36), 256, SMEM1_BYTES>>>(p_vph, p_wu16, p_mw);
    wg_output4<<<WPLANE4 / 256, 256>>>(p_mw, cba_cb, p_convh);
    // 6. q projection
    gemm_h1h<<<dim3(4, 512), 256, SMEM1_BYTES>>>(p_convh, p_convh, 512, 512,
        p_w16 + W16_MIXQP, mixqp_b, mixqp_b, mixqp_b, p_qf16, p_qf16, p_qf16);
    // 7. rgbk|rgbv from x; infk|infv from x2 (N=1024 each)
    gemm_h1h<<<dim3(8, 512), 256, SMEM1_BYTES>>>(p_x16, p_x16, 512, 512,
        p_w16 + W16_RGBK, rgbk_b, rgbv_b, rgbv_b, p_rgbk16, p_rgbv16, p_rgbv16);
    gemm_h1h<<<dim3(8, 512), 256, SMEM1_BYTES>>>(p_x216, p_x216, 512, 512,
        p_w16 + W16_INFK, infk_b, infv_b, infv_b, p_infk16, p_infv16, p_infv16);
    // 8. fused dual masked attention (HMMA)
    attn_dual<<<BB * NH, 256, DU_P + 4*APL>>>(p_qf16, p_infk16, p_rgbk16,
        p_rgbv16, p_infv16, aw, mask, p_aAh, p_aAl, p_aBh, p_aBl, 0.125f);
    // 9. output projections (fp16x2, fp32 out into d_out)
    gemm_h2f<<<dim3(4, 512), 256, SMEM2_BYTES>>>(p_aAh, p_aAl, 512,
                                                 p_w16 + W16_RGBO, rgbo_b, out);
    gemm_h2f<<<dim3(4, 512), 256, SMEM2_BYTES>>>(p_aBh, p_aBl, 512,
                                                 p_w16 + W16_INFO, info_b, out + NELEM);
}

// round 16
// speedup vs baseline: 7.3099x; 1.1027x over previous
#include <cuda_runtime.h>
#include <cuda_fp16.h>
#include <cstdint>

#define BB 1024
#define NQQ 64
#define CC 512
#define NH 8
#define NELEM (BB*NQQ*CC)       // 33554432
#define PER_BATCH (NQQ*CC)      // 32768
#define WPLANE4 (4096*512)      // 2097152

typedef __half fp16;

// ---------------- scratch ---------------------------------------------------
__device__ float g_xmean[PER_BATCH];

__device__ fp16 g_x16[NELEM], g_x216[NELEM];
__device__ fp16 g_mixq16[NELEM];
__device__ fp16 g_mqth[NELEM];
__device__ fp16 g_q16[NELEM], g_k16[NELEM], g_v16[NELEM];
__device__ fp16 g_yt16[NELEM];
__device__ fp16 g_convh[NELEM];
__device__ fp16 g_qf16[NELEM];
__device__ fp16 g_rgbk16[NELEM], g_infk16[NELEM];
__device__ fp16 g_rgbv16[NELEM], g_infv16[NELEM];
__device__ fp16 g_aAh[NELEM];
__device__ fp16 g_aBh[NELEM];
__device__ fp16 g_vph[36 * WPLANE4];
__device__ fp16 g_wu16[36 * 262144];
__device__ fp16 g_mw[36 * WPLANE4];

// fp16 weight pool
#define W16_CAQ   0
#define W16_CAK   262144
#define W16_CAV   524288
#define W16_MIXQP 786432
#define W16_RGBK  1048576
#define W16_RGBV  1310720
#define W16_INFK  1572864
#define W16_INFV  1835008
#define W16_MIXQ  2097152
#define W16_RGBO  2621440
#define W16_INFO  2883584
__device__ fp16 g_w16[3145728];

// ---------------- PTX helpers ----------------------------------------------
__device__ __forceinline__ uint32_t smem_u32(const void* p) {
    uint32_t a;
    asm("{ .reg .u64 t; cvta.to.shared.u64 t, %1; cvt.u32.u64 %0, t; }" : "=r"(a) : "l"(p));
    return a;
}
#define CP16(dst, src) \
    asm volatile("cp.async.cg.shared.global [%0], [%1], 16;" :: "r"(dst), "l"(src))
#define CPCOMMIT() asm volatile("cp.async.commit_group;" ::: "memory")
#define CPWAIT1()  asm volatile("cp.async.wait_group 1;" ::: "memory")

#define LDSM4(r, a) \
    asm volatile("ldmatrix.sync.aligned.m8n8.x4.shared.b16 {%0,%1,%2,%3}, [%4];" \
        : "=r"((r)[0]), "=r"((r)[1]), "=r"((r)[2]), "=r"((r)[3]) : "r"(a))

#define LDSM4T(r, a) \
    asm volatile("ldmatrix.sync.aligned.m8n8.x4.trans.shared.b16 {%0,%1,%2,%3}, [%4];" \
        : "=r"((r)[0]), "=r"((r)[1]), "=r"((r)[2]), "=r"((r)[3]) : "r"(a))

#define MMA16816H(d, a, b0, b1) \
    asm volatile("mma.sync.aligned.m16n8k16.row.col.f32.f16.f16.f32 " \
        "{%0,%1,%2,%3}, {%4,%5,%6,%7}, {%8,%9}, {%0,%1,%2,%3};" \
        : "+f"((d)[0]), "+f"((d)[1]), "+f"((d)[2]), "+f"((d)[3]) \
        : "r"((a)[0]), "r"((a)[1]), "r"((a)[2]), "r"((a)[3]), "r"(b0), "r"(b1))

#define PLANE_B   18432
#define STAGE1_B  (2*PLANE_B)
#define SMEM1_BYTES (3*STAGE1_B)        // 110592
#define APL 9216                        // attention plane pitch: 64 rows * 144B

// ---------------- stage loader (GEMM) ---------------------------------------
__device__ __forceinline__ void gemm1_load_stage(
    uint32_t smb, int stage, int t, int bm, int bn, int tid,
    const fp16* A, const fp16* A2, int ksplit, int K, const fp16* W)
{
    const int k0 = t << 6;
    const fp16* pA; int astr, acol;
    if (k0 < ksplit) { pA = A;  astr = ksplit;     acol = k0; }
    else             { pA = A2; astr = K - ksplit; acol = k0 - ksplit; }
    const uint32_t sb = smb + stage * STAGE1_B;
#pragma unroll
    for (int i = 0; i < 8; i++) {
        const int c = i * 256 + tid;
        const int plane = c >> 10, idx = c & 1023;
        const int row = idx >> 3, kc = idx & 7;
        const uint32_t dst = sb + plane * PLANE_B + row * 144 + kc * 16;
        const fp16* src = (plane == 0)
            ? pA + (size_t)(bm * 128 + row) * astr + acol + kc * 8
            : W + (size_t)(bn * 128 + row) * K + k0 + kc * 8;
        CP16(dst, src);
    }
}

// ---------------- compute (register-pipelined) + epilogues -------------------
#define LD_FRAGS1(ks_, buf_)                                                    \
    {                                                                           \
        _Pragma("unroll")                                                       \
        for (int mt = 0; mt < 2; mt++)                                          \
            LDSM4(fa[buf_][mt], abase + mt * (16 * 144) + (ks_) * 32);          \
        _Pragma("unroll")                                                       \
        for (int n2 = 0; n2 < 4; n2++)                                          \
            LDSM4(fb[buf_][n2], bbase + n2 * (16 * 144) + (ks_) * 32);          \
    }

#define COMPUTE_STAGE1(stg)                                                     \
    {                                                                           \
        const uint32_t sb = smb + (stg) * STAGE1_B;                             \
        const uint32_t abase = sb + (warp_m * 32 + (lane & 15)) * 144           \
                                  + ((lane >> 4) * 16);                         \
        const uint32_t bbase = sb + PLANE_B                                     \
                                  + (warp_n * 64 + (lane & 15)) * 144           \
                                  + ((lane >> 4) * 16);                         \
        uint32_t fa[2][2][4], fb[2][4][4];                                      \
        LD_FRAGS1(0, 0);                                                        \
        _Pragma("unroll")                                                       \
        for (int ks = 0; ks < 4; ks++) {                                        \
            const int cur = ks & 1, nxt = cur ^ 1;                              \
            if (ks < 3) LD_FRAGS1(ks + 1, nxt);                                 \
            _Pragma("unroll")                                                   \
            for (int mt = 0; mt < 2; mt++)                                      \
                _Pragma("unroll")                                               \
                for (int nt = 0; nt < 8; nt++) {                                \
                    const int n2 = nt >> 1, s = nt & 1;                         \
                    MMA16816H(acc[mt][nt], fa[cur][mt],                         \
                              fb[cur][n2][s], fb[cur][n2][2 + s]);              \
                }                                                               \
        }                                                                       \
    }

#define EPILOGUE_F()                                                            \
    {                                                                           \
        const int lrow = lane >> 2, lcol = (lane & 3) * 2;                      \
        _Pragma("unroll")                                                       \
        for (int mt = 0; mt < 2; mt++)                                          \
            _Pragma("unroll")                                                   \
            for (int nt = 0; nt < 8; nt++) {                                    \
                const int row = bm * 128 + warp_m * 32 + mt * 16 + lrow;        \
                const int col = bn * 128 + warp_n * 64 + nt * 8 + lcol;         \
                const float b0 = bias[col], b1 = bias[col + 1];                 \
                float2 v0 = make_float2(acc[mt][nt][0] + b0, acc[mt][nt][1] + b1); \
                float2 v1 = make_float2(acc[mt][nt][2] + b0, acc[mt][nt][3] + b1); \
                *(float2*)(C + (size_t)row * 512 + col) = v0;                   \
                *(float2*)(C + (size_t)(row + 8) * 512 + col) = v1;             \
            }                                                                   \
    }

#define EPILOGUE_HB_SPLIT()                                                     \
    {                                                                           \
        const int tsel = bn >> 2;                                               \
        fp16* C = (tsel == 0) ? C0 : ((tsel == 1) ? C1 : C2);                   \
        const float* bias = (tsel == 0) ? b0p : ((tsel == 1) ? b1p : b2p);      \
        const int bnl = bn & 3;                                                 \
        const int lrow = lane >> 2, lcol = (lane & 3) * 2;                      \
        _Pragma("unroll")                                                       \
        for (int mt = 0; mt < 2; mt++)                                          \
            _Pragma("unroll")                                                   \
            for (int nt = 0; nt < 8; nt++) {                                    \
                const int row = bm * 128 + warp_m * 32 + mt * 16 + lrow;        \
                const int col = bnl * 128 + warp_n * 64 + nt * 8 + lcol;        \
                const float b0 = bias[col], b1 = bias[col + 1];                 \
                *(__half2*)(C + (size_t)row * 512 + col) =                      \
                    __halves2half2(__float2half(acc[mt][nt][0] + b0),           \
                                   __float2half(acc[mt][nt][1] + b1));          \
                *(__half2*)(C + (size_t)(row + 8) * 512 + col) =                \
                    __halves2half2(__float2half(acc[mt][nt][2] + b0),           \
                                   __float2half(acc[mt][nt][3] + b1));          \
            }                                                                   \
    }

#define EPILOGUE_H()                                                            \
    {                                                                           \
        const int lrow = lane >> 2, lcol = (lane & 3) * 2;                      \
        _Pragma("unroll")                                                       \
        for (int mt = 0; mt < 2; mt++)                                          \
            _Pragma("unroll")                                                   \
            for (int nt = 0; nt < 8; nt++) {                                    \
                const int row = bm * 128 + warp_m * 32 + mt * 16 + lrow;        \
                const int col = bn * 128 + warp_n * 64 + nt * 8 + lcol;         \
                *(__half2*)(C + (size_t)row * 512 + col) =                      \
                    __halves2half2(__float2half(acc[mt][nt][0]),                \
                                   __float2half(acc[mt][nt][1]));               \
                *(__half2*)(C + (size_t)(row + 8) * 512 + col) =                \
                    __halves2half2(__float2half(acc[mt][nt][2]),                \
                                   __float2half(acc[mt][nt][3]));               \
            }                                                                   \
    }

#define MAINLOOP(LOADER, COMPUTE, ...)                                          \
    {                                                                           \
        LOADER(smb, 0, 0, bm, bn, tid, __VA_ARGS__);                            \
        CPCOMMIT();                                                             \
        LOADER(smb, 1, 1, bm, bn, tid, __VA_ARGS__);                            \
        CPCOMMIT();                                                             \
        int s_cur = 0, s_nxt = 2;                                               \
        for (int t = 0; t < NT; t++) {                                          \
            CPWAIT1();                                                          \
            __syncthreads();                                                    \
            if (t + 2 < NT)                                                     \
                LOADER(smb, s_nxt, t + 2, bm, bn, tid, __VA_ARGS__);            \
            CPCOMMIT();                                                         \
            COMPUTE(s_cur);                                                     \
            s_cur = (s_cur == 2) ? 0 : s_cur + 1;                               \
            s_nxt = (s_nxt == 2) ? 0 : s_nxt + 1;                               \
        }                                                                       \
    }

#define ACC_INIT()                                                              \
    float acc[2][8][4];                                                         \
    _Pragma("unroll")                                                           \
    for (int i = 0; i < 2; i++)                                                 \
        _Pragma("unroll")                                                       \
        for (int j = 0; j < 8; j++)                                             \
            _Pragma("unroll")                                                   \
            for (int k = 0; k < 4; k++) acc[i][j][k] = 0.f;

#define GEMM_PREAMBLE()                                                         \
    extern __shared__ char sm[];                                                \
    const uint32_t smb = smem_u32(sm);                                          \
    const int tid = threadIdx.x, lane = tid & 31, wid = tid >> 5;               \
    const int warp_m = wid & 3, warp_n = wid >> 2;                              \
    const int bn = blockIdx.x, bm = blockIdx.y;

// ---------------- fp16x1 GEMM, split fp16 out -------------------------------
__global__ __launch_bounds__(256) void gemm_h1h(
    const fp16* __restrict__ A, const fp16* __restrict__ A2,
    int ksplit, int K, const fp16* __restrict__ W,
    const float* __restrict__ b0p, const float* __restrict__ b1p,
    const float* __restrict__ b2p,
    fp16* __restrict__ C0, fp16* __restrict__ C1, fp16* __restrict__ C2)
{
    GEMM_PREAMBLE();
    ACC_INIT();
    const int NT = K >> 6;
    MAINLOOP(gemm1_load_stage, COMPUTE_STAGE1, A, A2, ksplit, K, W);
    EPILOGUE_HB_SPLIT();
}

// ---------------- fp16x1 GEMM, fp32 out (final projections) -----------------
__global__ __launch_bounds__(256) void gemm_h1f(
    const fp16* __restrict__ A, const fp16* __restrict__ A2,
    int ksplit, int K, const fp16* __restrict__ W,
    const float* __restrict__ bias, float* __restrict__ C)
{
    GEMM_PREAMBLE();
    ACC_INIT();
    const int NT = K >> 6;
    MAINLOOP(gemm1_load_stage, COMPUTE_STAGE1, A, A2, ksplit, K, W);
    EPILOGUE_F();
}

// ---------------- winograd F(4x4) batched GEMM ------------------------------
__global__ __launch_bounds__(256) void wino_gemm4(
    const fp16* __restrict__ V, const fp16* __restrict__ U, fp16* __restrict__ Mb)
{
    extern __shared__ char sm[];
    const uint32_t smb = smem_u32(sm);
    const int tid = threadIdx.x, lane = tid & 31, wid = tid >> 5;
    const int warp_m = wid & 3, warp_n = wid >> 2;
    const int bn = blockIdx.x, bm = blockIdx.y, z = blockIdx.z;
    const fp16* A = V + (size_t)z * WPLANE4;
    const fp16* W = U + (size_t)z * 262144;
    fp16* C = Mb + (size_t)z * WPLANE4;
    ACC_INIT();
    const int NT = 8;
    MAINLOOP(gemm1_load_stage, COMPUTE_STAGE1, A, A, 512, 512, W);
    EPILOGUE_H();
}

// ---------------- winograd F(4x4) transforms --------------------------------
__device__ __forceinline__ void gmul6(const float x0, const float x1, const float x2,
                                      float* y)
{
    y[0] = 0.25f * x0;
    y[1] = (-1.0f / 6.0f) * (x0 + x1 + x2);
    y[2] = (-1.0f / 6.0f) * (x0 - x1 + x2);
    y[3] = (1.0f / 24.0f) * (x0 + 2.0f * x1 + 4.0f * x2);
    y[4] = (1.0f / 24.0f) * (x0 - 2.0f * x1 + 4.0f * x2);
    y[5] = x2;
}

__global__ void wg_weight4(const float* __restrict__ cw, fp16* __restrict__ u16)
{
    const int idx = blockIdx.x * 256 + threadIdx.x;
    const int o = idx >> 9, c = idx & 511;
    const float* g = cw + (size_t)(o * 512 + c) * 9;
    float P[6][3];
#pragma unroll
    for (int kj = 0; kj < 3; kj++) {
        float col[6];
        gmul6(g[0 * 3 + kj], g[1 * 3 + kj], g[2 * 3 + kj], col);
#pragma unroll
        for (int r = 0; r < 6; r++) P[r][kj] = col[r];
    }
#pragma unroll
    for (int r = 0; r < 6; r++) {
        float U[6];
        gmul6(P[r][0], P[r][1], P[r][2], U);
#pragma unroll
        for (int cc = 0; cc < 6; cc++)
            u16[(size_t)(r * 6 + cc) * 262144 + o * 512 + c] = __float2half(U[cc]);
    }
}

__device__ __forceinline__ void btmul6(const float* x, float* y)
{
    y[0] = 4.0f * x[0] - 5.0f * x[2] + x[4];
    y[1] = -4.0f * x[1] - 4.0f * x[2] + x[3] + x[4];
    y[2] = 4.0f * x[1] - 4.0f * x[2] - x[3] + x[4];
    y[3] = -2.0f * x[1] - x[2] + 2.0f * x[3] + x[4];
    y[4] = 2.0f * x[1] - x[2] - 2.0f * x[3] + x[4];
    y[5] = 4.0f * x[1] - 5.0f * x[3] + x[5];
}

__global__ void wg_input4(const fp16* __restrict__ yt, fp16* __restrict__ vh)
{
    const int idx = blockIdx.x * 256 + threadIdx.x;
    const int c = idx & 511;
    const int m = idx >> 9;
    const int b = m >> 2, t = m & 3;
    const int ti = t >> 1, tj = t & 1;
    const int r0 = 4 * ti - 1, c0 = 4 * tj - 1;
    float d[6][6];
#pragma unroll
    for (int r = 0; r < 6; r++) {
        const int ir = r0 + r;
#pragma unroll
        for (int cc = 0; cc < 6; cc++) {
            const int jc = c0 + cc;
            d[r][cc] = ((unsigned)ir < 8u && (unsigned)jc < 8u)
                ? __half2float(yt[((size_t)b * 64 + ir * 8 + jc) * 512 + c]) : 0.f;
        }
    }
    float p[6][6];
#pragma unroll
    for (int cc = 0; cc < 6; cc++) {
        float col[6], out[6];
#pragma unroll
        for (int r = 0; r < 6; r++) col[r] = d[r][cc];
        btmul6(col, out);
#pragma unroll
        for (int r = 0; r < 6; r++) p[r][cc] = out[r];
    }
#pragma unroll
    for (int r = 0; r < 6; r++) {
        float V[6];
        btmul6(p[r], V);
#pragma unroll
        for (int cc = 0; cc < 6; cc++)
            vh[(size_t)(r * 6 + cc) * WPLANE4 + (size_t)m * 512 + c] = __float2half(V[cc]);
    }
}

__device__ __forceinline__ void atmul6(const float* x, float* z)
{
    z[0] = x[0] + x[1] + x[2] + x[3] + x[4];
    z[1] = x[1] - x[2] + 2.0f * x[3] - 2.0f * x[4];
    z[2] = x[1] + x[2] + 4.0f * x[3] + 4.0f * x[4];
    z[3] = x[1] - x[2] + 8.0f * x[3] - 8.0f * x[4] + x[5];
}

__global__ void wg_output4(const fp16* __restrict__ Mb, const float* __restrict__ bias,
                           fp16* __restrict__ ch)
{
    const int idx = blockIdx.x * 256 + threadIdx.x;
    const int o = idx & 511;
    const int m = idx >> 9;
    const int b = m >> 2, t = m & 3;
    const int ti = t >> 1, tj = t & 1;
    float M[6][6];
#pragma unroll
    for (int f = 0; f < 36; f++)
        M[f / 6][f % 6] = __half2float(Mb[(size_t)f * WPLANE4 + (size_t)m * 512 + o]);
    float P[4][6];
#pragma unroll
    for (int cc = 0; cc < 6; cc++) {
        float col[6], out[4];
#pragma unroll
        for (int r = 0; r < 6; r++) col[r] = M[r][cc];
        atmul6(col, out);
#pragma unroll
        for (int r = 0; r < 4; r++) P[r][cc] = out[r];
    }
    const float bv = bias[o];
#pragma unroll
    for (int di = 0; di < 4; di++) {
        float O[4];
        atmul6(P[di], O);
        const size_t s0 = ((size_t)b * 64 + (4 * ti + di) * 8 + 4 * tj) * 512 + o;
#pragma unroll
        for (int dj = 0; dj < 4; dj++)
            ch[s0 + (size_t)dj * 512] = __float2half(O[dj] + bv);
    }
}

// ---------------- conversions -----------------------------------------------
__global__ void cvt_inputs(const float* __restrict__ x, const float* __restrict__ x2,
                           fp16* __restrict__ dx, fp16* __restrict__ dx2)
{
    const int i = blockIdx.x * 256 + threadIdx.x;
    const float* s = blockIdx.y ? x2 : x;
    fp16* d = blockIdx.y ? dx2 : dx;
    float4 v = ((const float4*)s)[i];
    ((__half2*)d)[i * 2 + 0] = __halves2half2(__float2half(v.x), __float2half(v.y));
    ((__half2*)d)[i * 2 + 1] = __halves2half2(__float2half(v.z), __float2half(v.w));
}

__global__ void wcvt_all(
    const float* w0, const float* w1, const float* w2, const float* w3,
    const float* w4, const float* w5, const float* w6, const float* w7,
    const float* w8, const float* w9, const float* w10, fp16* __restrict__ dst)
{
    const int blk = blockIdx.x;
    const float* src;
    size_t doff;
    int lb;
    if (blk < 512) { src = w0; doff = W16_MIXQ; lb = blk; }
    else {
        const int t = (blk - 512) >> 8;
        lb = (blk - 512) & 255;
        switch (t) {
            case 0: src = w1;  doff = W16_CAQ;   break;
            case 1: src = w2;  doff = W16_CAK;   break;
            case 2: src = w3;  doff = W16_CAV;   break;
            case 3: src = w4;  doff = W16_MIXQP; break;
            case 4: src = w5;  doff = W16_RGBK;  break;
            case 5: src = w6;  doff = W16_RGBV;  break;
            case 6: src = w7;  doff = W16_INFK;  break;
            case 7: src = w8;  doff = W16_INFV;  break;
            case 8: src = w9;  doff = W16_RGBO;  break;
            default: src = w10; doff = W16_INFO;  break;
        }
    }
    const int i = lb * 256 + threadIdx.x;
    float4 v = ((const float4*)src)[i];
    ((__half2*)(dst + doff))[i * 2 + 0] = __halves2half2(__float2half(v.x), __float2half(v.y));
    ((__half2*)(dst + doff))[i * 2 + 1] = __halves2half2(__float2half(v.z), __float2half(v.w));
}

// ---------------- tensor-core attention helpers ------------------------------
__device__ __forceinline__ void ld_tile64(const fp16* g, size_t base, char* sp, int tid)
{
#pragma unroll
    for (int i = tid; i < 512; i += 256) {
        const int r = i >> 3, c = i & 7;
        *(uint4*)(sp + r * 144 + c * 16) = *(const uint4*)(g + base + (size_t)r * 512 + c * 8);
    }
}

__device__ __forceinline__ void softmax64(float* S, int tid)
{
    const int warp = tid >> 5, lane = tid & 31;
    for (int r = warp * 8; r < warp * 8 + 8; r++) {
        float v0 = S[r * 64 + lane];
        float v1 = S[r * 64 + 32 + lane];
        float m = fmaxf(v0, v1);
#pragma unroll
        for (int o = 16; o > 0; o >>= 1) m = fmaxf(m, __shfl_xor_sync(0xffffffffu, m, o));
        float e0 = __expf(v0 - m);
        float e1 = __expf(v1 - m);
        float sum = e0 + e1;
#pragma unroll
        for (int o = 16; o > 0; o >>= 1) sum += __shfl_xor_sync(0xffffffffu, sum, o);
        float inv = 1.0f / sum;
        S[r * 64 + lane]      = e0 * inv;
        S[r * 64 + 32 + lane] = e1 * inv;
    }
}

// ---------------- CA attention (HMMA) + fused combine ------------------------
#define CA_SMEM (3*APL + 16384 + APL)   // 53248
__global__ __launch_bounds__(256, 2) void attn_ca(
    const fp16* __restrict__ Q, const fp16* __restrict__ Kp, const fp16* __restrict__ Vp,
    const float* __restrict__ XM, const fp16* __restrict__ MQ,
    const float* __restrict__ GM, fp16* __restrict__ YT, float scale)
{
    extern __shared__ char smc[];
    const uint32_t smb = smem_u32(smc);
    float* S = (float*)(smc + 3 * APL);
    const int tid = threadIdx.x, lane = tid & 31, wid = tid >> 5;
    const int warp_m = wid & 3, warp_n = wid >> 2;
    const int bh = blockIdx.x;
    const int b = bh >> 3, h = bh & 7;
    const size_t base = (size_t)b * 64 * 512 + h * 64;

    ld_tile64(Q, base, smc, tid);
    ld_tile64(Kp, base, smc + APL, tid);
    ld_tile64(Vp, base, smc + 2 * APL, tid);
    __syncthreads();

    float acc[4][4];
#pragma unroll
    for (int i = 0; i < 4; i++)
#pragma unroll
        for (int j = 0; j < 4; j++) acc[i][j] = 0.f;
    {
        const uint32_t qb = smb + (warp_m * 16 + (lane & 15)) * 144 + (lane >> 4) * 16;
        const uint32_t kb = smb + APL + (warp_n * 32 + (lane & 15)) * 144 + (lane >> 4) * 16;
#pragma unroll
        for (int ks = 0; ks < 4; ks++) {
            uint32_t fa[4], fb[2][4];
            LDSM4(fa, qb + ks * 32);
#pragma unroll
            for (int n2 = 0; n2 < 2; n2++)
                LDSM4(fb[n2], kb + n2 * (16 * 144) + ks * 32);
#pragma unroll
            for (int nt = 0; nt < 4; nt++) {
                const int n2 = nt >> 1, s = nt & 1;
                MMA16816H(acc[nt], fa, fb[n2][s], fb[n2][2 + s]);
            }
        }
    }
    {
        const int r0 = warp_m * 16 + (lane >> 2);
#pragma unroll
        for (int nt = 0; nt < 4; nt++) {
            const int col = warp_n * 32 + nt * 8 + (lane & 3) * 2;
            S[r0 * 64 + col]     = acc[nt][0] * scale;
            S[r0 * 64 + col + 1] = acc[nt][1] * scale;
            S[(r0 + 8) * 64 + col]     = acc[nt][2] * scale;
            S[(r0 + 8) * 64 + col + 1] = acc[nt][3] * scale;
        }
    }
    __syncthreads();
    softmax64(S, tid);
    __syncthreads();
    {
        char* Ph = smc + 3 * APL + 16384;
        for (int i = tid; i < 4096; i += 256) {
            const int r = i >> 6, c = i & 63;
            *(fp16*)(Ph + r * 144 + c * 2) = __float2half(S[i]);
        }
    }
    __syncthreads();
    float o[4][4];
#pragma unroll
    for (int i = 0; i < 4; i++)
#pragma unroll
        for (int j = 0; j < 4; j++) o[i][j] = 0.f;
    {
        const uint32_t pb = smb + 3 * APL + 16384
                          + (warp_m * 16 + (lane & 15)) * 144 + (lane >> 4) * 16;
        const uint32_t vb = smb + 2 * APL + (lane & 15) * 144 + (lane >> 4) * 16;
#pragma unroll
        for (int ks = 0; ks < 4; ks++) {
            uint32_t fa[4], fv[2][4];
            LDSM4(fa, pb + ks * 32);
#pragma unroll
            for (int n2 = 0; n2 < 2; n2++)
                LDSM4T(fv[n2], vb + ks * (16 * 144) + warp_n * 64 + n2 * 32);
#pragma unroll
            for (int nt = 0; nt < 4; nt++) {
                const int n2 = nt >> 1, s = nt & 1;
                MMA16816H(o[nt], fa, fv[n2][2 * s], fv[n2][2 * s + 1]);
            }
        }
    }
    const float g = GM[0];
    {
        const int r0 = warp_m * 16 + (lane >> 2);
#pragma unroll
        for (int nt = 0; nt < 4; nt++) {
            const int col = warp_n * 32 + nt * 8 + (lane & 3) * 2;
#pragma unroll
            for (int hh = 0; hh < 2; hh++) {
                const int row = r0 + hh * 8;
                const size_t off = (size_t)(b * 64 + row) * 512 + h * 64 + col;
                const int mo = (int)(off & (PER_BATCH - 1));
                float2 xm = *(const float2*)(XM + mo);
                float2 mq = __half22float2(*(const __half2*)(MQ + off));
                *(__half2*)(YT + off) = __halves2half2(
                    __float2half(xm.x + g * o[nt][2 * hh]     + mq.x),
                    __float2half(xm.y + g * o[nt][2 * hh + 1] + mq.y));
            }
        }
    }
}

// ---------------- dual masked attention (HMMA, fp16 hi out) ------------------
#define DU_SA   (4*APL)
#define DU_SB   (4*APL + 16384)
#define DU_P    (4*APL + 32768)
#define DU_SMEM (DU_P + 4*APL)
__global__ __launch_bounds__(256, 2) void attn_dual(
    const fp16* __restrict__ Q,
    const fp16* __restrict__ IK, const fp16* __restrict__ RK,
    const fp16* __restrict__ RV, const fp16* __restrict__ IV,
    const float* __restrict__ AW, const int* __restrict__ MK,
    fp16* __restrict__ AH, fp16* __restrict__ BH, float scale)
{
    extern __shared__ char smc[];
    const uint32_t smb = smem_u32(smc);
    float* SA = (float*)(smc + DU_SA);
    float* SB = (float*)(smc + DU_SB);
    const float NEG_INF = __int_as_float(0xff800000);
    const int tid = threadIdx.x, lane = tid & 31, wid = tid >> 5;
    const int warp_m = wid & 3, warp_n = wid >> 2;
    const int bh = blockIdx.x;
    const int b = bh >> 3, h = bh & 7;
    const size_t base = (size_t)b * 64 * 512 + h * 64;

    ld_tile64(Q, base, smc, tid);
    ld_tile64(IK, base, smc + APL, tid);
    ld_tile64(RK, base, smc + 2 * APL, tid);
    __syncthreads();

    float accA[4][4], accB[4][4];
#pragma unroll
    for (int i = 0; i < 4; i++)
#pragma unroll
        for (int j = 0; j < 4; j++) { accA[i][j] = 0.f; accB[i][j] = 0.f; }
    {
        const uint32_t qb = smb + (warp_m * 16 + (lane & 15)) * 144 + (lane >> 4) * 16;
        const uint32_t ib = smb + APL + (warp_n * 32 + (lane & 15)) * 144 + (lane >> 4) * 16;
        const uint32_t rb = smb + 2 * APL + (warp_n * 32 + (lane & 15)) * 144 + (lane >> 4) * 16;
#pragma unroll
        for (int ks = 0; ks < 4; ks++) {
            uint32_t fa[4], fi[2][4], fr[2][4];
            LDSM4(fa, qb + ks * 32);
#pragma unroll
            for (int n2 = 0; n2 < 2; n2++) {
                LDSM4(fi[n2], ib + n2 * (16 * 144) + ks * 32);
                LDSM4(fr[n2], rb + n2 * (16 * 144) + ks * 32);
            }
#pragma unroll
            for (int nt = 0; nt < 4; nt++) {
                const int n2 = nt >> 1, s = nt & 1;
                MMA16816H(accA[nt], fa, fi[n2][s], fi[n2][2 + s]);
                MMA16816H(accB[nt], fa, fr[n2][s], fr[n2][2 + s]);
            }
        }
    }
    {
        const size_t ab = (size_t)bh * 4096;
        const int r0 = warp_m * 16 + (lane >> 2);
#pragma unroll
        for (int nt = 0; nt < 4; nt++) {
            const int col = warp_n * 32 + nt * 8 + (lane & 3) * 2;
#pragma unroll
            for (int hh = 0; hh < 2; hh++) {
                const int row = r0 + hh * 8;
                const size_t off = ab + (size_t)row * 64 + col;
                float2 w = *(const float2*)(AW + off);
                int2 m = *(const int2*)(MK + off);
                SA[row * 64 + col]     = m.x ? NEG_INF : accA[nt][2 * hh] * scale * w.x;
                SA[row * 64 + col + 1] = m.y ? NEG_INF : accA[nt][2 * hh + 1] * scale * w.y;
                SB[row * 64 + col]     = m.x ? NEG_INF : accB[nt][2 * hh] * scale * w.x;
                SB[row * 64 + col + 1] = m.y ? NEG_INF : accB[nt][2 * hh + 1] * scale * w.y;
            }
        }
    }
    __syncthreads();
    softmax64(SA, tid);
    softmax64(SB, tid);
    __syncthreads();
    {
        char* P = smc + DU_P;
        for (int i = tid; i < 4096; i += 256) {
            const int r = i >> 6, c = i & 63;
            float va = SA[i];
            fp16 ha = __float2half(va);
            *(fp16*)(P + r * 144 + c * 2)            = ha;
            *(fp16*)(P + APL + r * 144 + c * 2)      = __float2half(va - __half2float(ha));
            float vb = SB[i];
            fp16 hb = __float2half(vb);
            *(fp16*)(P + 2 * APL + r * 144 + c * 2)  = hb;
            *(fp16*)(P + 3 * APL + r * 144 + c * 2)  = __float2half(vb - __half2float(hb));
        }
    }
#pragma unroll
    for (int pass = 0; pass < 2; pass++) {
        ld_tile64(pass ? IV : RV, base, smc + 3 * APL, tid);
        __syncthreads();
        float o[4][4];
#pragma unroll
        for (int i = 0; i < 4; i++)
#pragma unroll
            for (int j = 0; j < 4; j++) o[i][j] = 0.f;
        const uint32_t ph = smb + DU_P + (pass ? 2 * APL : 0)
                          + (warp_m * 16 + (lane & 15)) * 144 + (lane >> 4) * 16;
        const uint32_t vb = smb + 3 * APL + (lane & 15) * 144 + (lane >> 4) * 16;
#pragma unroll
        for (int ks = 0; ks < 4; ks++) {
            uint32_t fah[4], fal[4], fv[2][4];
            LDSM4(fah, ph + ks * 32);
            LDSM4(fal, ph + APL + ks * 32);
#pragma unroll
            for (int n2 = 0; n2 < 2; n2++)
                LDSM4T(fv[n2], vb + ks * (16 * 144) + warp_n * 64 + n2 * 32);
#pragma unroll
            for (int nt = 0; nt < 4; nt++) {
                const int n2 = nt >> 1, s = nt & 1;
                MMA16816H(o[nt], fah, fv[n2][2 * s], fv[n2][2 * s + 1]);
                MMA16816H(o[nt], fal, fv[n2][2 * s], fv[n2][2 * s + 1]);
            }
        }
        fp16* OH = pass ? BH : AH;
        const int r0 = warp_m * 16 + (lane >> 2);
#pragma unroll
        for (int nt = 0; nt < 4; nt++) {
            const int col = warp_n * 32 + nt * 8 + (lane & 3) * 2;
#pragma unroll
            for (int hh = 0; hh < 2; hh++) {
                const int row = r0 + hh * 8;
                const size_t off = (size_t)(b * 64 + row) * 512 + h * 64 + col;
                *(__half2*)(OH + off) = __halves2half2(
                    __float2half(o[nt][2 * hh]), __float2half(o[nt][2 * hh + 1]));
            }
        }
        __syncthreads();
    }
}

// ---------------- small helpers -------------------------------------------
__global__ void transpose_kernel(const fp16* __restrict__ src, fp16* __restrict__ dst)
{
    __shared__ float tile[32][33];
    const int bz = blockIdx.z;
    const int c0 = blockIdx.x * 32, s0 = blockIdx.y * 32;
    const fp16* S = src + (size_t)bz * PER_BATCH;
    const size_t dbase = (size_t)bz * PER_BATCH;
    for (int r = threadIdx.y; r < 32; r += 8)
        tile[r][threadIdx.x] = __half2float(S[(c0 + r) * 64 + s0 + threadIdx.x]);
    __syncthreads();
    for (int r = threadIdx.y; r < 32; r += 8)
        dst[dbase + (size_t)(s0 + r) * 512 + c0 + threadIdx.x]
            = __float2half(tile[threadIdx.x][r]);
}

__global__ void xmean_kernel(const fp16* __restrict__ mqt, float* __restrict__ xm)
{
    const int i = blockIdx.x * 256 + threadIdx.x;
    float sum = 0.f;
#pragma unroll 8
    for (int b = 0; b < BB; b++)
        sum += __half2float(mqt[(size_t)b * PER_BATCH + i]);
    xm[i] = sum * (1.0f / (float)BB);
}

// ---------------- launch ----------------------------------------------------
extern "C" void kernel_launch(void* const* d_in, const int* in_sizes, int n_in,
                              void* d_out, int out_size)
{
    (void)in_sizes; (void)n_in; (void)out_size;
    const float* x        = (const float*)d_in[0];
    const float* x2       = (const float*)d_in[1];
    const float* aw       = (const float*)d_in[2];
    const int*   mask     = (const int*)d_in[3];
    const float* mixq_w   = (const float*)d_in[4];
    const float* mixq_b   = (const float*)d_in[5];
    const float* mixqp_w  = (const float*)d_in[6];
    const float* mixqp_b  = (const float*)d_in[7];
    const float* ca_qw    = (const float*)d_in[8];
    const float* ca_qb    = (const float*)d_in[9];
    const float* ca_kw    = (const float*)d_in[10];
    const float* ca_kb    = (const float*)d_in[11];
    const float* ca_vw    = (const float*)d_in[12];
    const float* ca_vb    = (const float*)d_in[13];
    const float* ca_gamma = (const float*)d_in[14];
    const float* cba_cw   = (const float*)d_in[15];
    const float* cba_cb   = (const float*)d_in[16];
    const float* rgbk_w   = (const float*)d_in[17];
    const float* rgbk_b   = (const float*)d_in[18];
    const float* rgbv_w   = (const float*)d_in[19];
    const float* rgbv_b   = (const float*)d_in[20];
    const float* rgbo_w   = (const float*)d_in[21];
    const float* rgbo_b   = (const float*)d_in[22];
    const float* infk_w   = (const float*)d_in[23];
    const float* infk_b   = (const float*)d_in[24];
    const float* infv_w   = (const float*)d_in[25];
    const float* infv_b   = (const float*)d_in[26];
    const float* info_w   = (const float*)d_in[27];
    const float* info_b   = (const float*)d_in[28];

    float* p_xmean;
    fp16 *p_x16, *p_x216, *p_mixq16, *p_mqth, *p_q16, *p_k16, *p_v16, *p_yt16;
    fp16 *p_convh, *p_qf16, *p_rgbk16, *p_infk16, *p_rgbv16, *p_infv16;
    fp16 *p_aAh, *p_aBh, *p_vph, *p_wu16, *p_w16, *p_mw;
    cudaGetSymbolAddress((void**)&p_xmean,  g_xmean);
    cudaGetSymbolAddress((void**)&p_x16,    g_x16);
    cudaGetSymbolAddress((void**)&p_x216,   g_x216);
    cudaGetSymbolAddress((void**)&p_mixq16, g_mixq16);
    cudaGetSymbolAddress((void**)&p_mqth,   g_mqth);
    cudaGetSymbolAddress((void**)&p_q16,    g_q16);
    cudaGetSymbolAddress((void**)&p_k16,    g_k16);
    cudaGetSymbolAddress((void**)&p_v16,    g_v16);
    cudaGetSymbolAddress((void**)&p_yt16,   g_yt16);
    cudaGetSymbolAddress((void**)&p_convh,  g_convh);
    cudaGetSymbolAddress((void**)&p_qf16,   g_qf16);
    cudaGetSymbolAddress((void**)&p_rgbk16, g_rgbk16);
    cudaGetSymbolAddress((void**)&p_infk16, g_infk16);
    cudaGetSymbolAddress((void**)&p_rgbv16, g_rgbv16);
    cudaGetSymbolAddress((void**)&p_infv16, g_infv16);
    cudaGetSymbolAddress((void**)&p_aAh,    g_aAh);
    cudaGetSymbolAddress((void**)&p_aBh,    g_aBh);
    cudaGetSymbolAddress((void**)&p_vph,    g_vph);
    cudaGetSymbolAddress((void**)&p_wu16,   g_wu16);
    cudaGetSymbolAddress((void**)&p_w16,    g_w16);
    cudaGetSymbolAddress((void**)&p_mw,     g_mw);

    float* out = (float*)d_out;

    cudaFuncSetAttribute(gemm_h1h,  cudaFuncAttributeMaxDynamicSharedMemorySize, SMEM1_BYTES);
    cudaFuncSetAttribute(gemm_h1f,  cudaFuncAttributeMaxDynamicSharedMemorySize, SMEM1_BYTES);
    cudaFuncSetAttribute(wino_gemm4, cudaFuncAttributeMaxDynamicSharedMemorySize, SMEM1_BYTES);
    cudaFuncSetAttribute(attn_ca,   cudaFuncAttributeMaxDynamicSharedMemorySize, CA_SMEM);
    cudaFuncSetAttribute(attn_dual, cudaFuncAttributeMaxDynamicSharedMemorySize, DU_SMEM);

    const int ACT4 = NELEM / 4;
    const int ABLK = ACT4 / 256;

    // fused conversions
    cvt_inputs<<<dim3(ABLK, 2), 256>>>(x, x2, p_x16, p_x216);
    wcvt_all<<<3072, 256>>>(mixq_w, ca_qw, ca_kw, ca_vw, mixqp_w, rgbk_w, rgbv_w,
                            infk_w, infv_w, rgbo_w, info_w, p_w16);
    wg_weight4<<<1024, 256>>>(cba_cw, p_wu16);

    // 1. mix_q (fp16x1, K=1024)
    gemm_h1h<<<dim3(4, 512), 256, SMEM1_BYTES>>>(p_x16, p_x216, 512, 1024,
        p_w16 + W16_MIXQ, mixq_b, mixq_b, mixq_b, p_mixq16, p_mixq16, p_mixq16);
    // 2. raw reinterpret -> transpose (fp16), xmean
    transpose_kernel<<<dim3(16, 2, BB), dim3(32, 8)>>>(p_mixq16, p_mqth);
    xmean_kernel<<<PER_BATCH / 256, 256>>>(p_mqth, p_xmean);
    // 3. CA q|k|v in ONE launch (N=1536)
    gemm_h1h<<<dim3(12, 512), 256, SMEM1_BYTES>>>(p_mqth, p_mqth, 512, 512,
        p_w16 + W16_CAQ, ca_qb, ca_kb, ca_vb, p_q16, p_k16, p_v16);
    // 4. CA attention (HMMA) + fused combine
    attn_ca<<<BB * NH, 256, CA_SMEM>>>(p_q16, p_k16, p_v16, p_xmean, p_mqth,
                                       ca_gamma, p_yt16, 0.125f);
    // 5. conv via winograd F(4x4,3x3)
    wg_input4<<<WPLANE4 / 256, 256>>>(p_yt16, p_vph);
    wino_gemm4<<<dim3(4, 32, 36), 256, SMEM1_BYTES>>>(p_vph, p_wu16, p_mw);
    wg_output4<<<WPLANE4 / 256, 256>>>(p_mw, cba_cb, p_convh);
    // 6. q projection
    gemm_h1h<<<dim3(4, 512), 256, SMEM1_BYTES>>>(p_convh, p_convh, 512, 512,
        p_w16 + W16_MIXQP, mixqp_b, mixqp_b, mixqp_b, p_qf16, p_qf16, p_qf16);
    // 7. rgbk|rgbv from x; infk|infv from x2 (N=1024 each)
    gemm_h1h<<<dim3(8, 512), 256, SMEM1_BYTES>>>(p_x16, p_x16, 512, 512,
        p_w16 + W16_RGBK, rgbk_b, rgbv_b, rgbv_b, p_rgbk16, p_rgbv16, p_rgbv16);
    gemm_h1h<<<dim3(8, 512), 256, SMEM1_BYTES>>>(p_x216, p_x216, 512, 512,
        p_w16 + W16_INFK, infk_b, infv_b, infv_b, p_infk16, p_infv16, p_infv16);
    // 8. fused dual masked attention (HMMA, hi out only)
    attn_dual<<<BB * NH, 256, DU_SMEM>>>(p_qf16, p_infk16, p_rgbk16,
        p_rgbv16, p_infv16, aw, mask, p_aAh, p_aBh, 0.125f);
    // 9. output projections (fp16x1, fp32 out into d_out)
    gemm_h1f<<<dim3(4, 512), 256, SMEM1_BYTES>>>(p_aAh, p_aAh, 512, 512,
                                                 p_w16 + W16_RGBO, rgbo_b, out);
    gemm_h1f<<<dim3(4, 512), 256, SMEM1_BYTES>>>(p_aBh, p_aBh, 512, 512,
                                                 p_w16 + W16_INFO, info_b, out + NELEM);
}